// round 12
// baseline (speedup 1.0000x reference)
#include <cuda_runtime.h>
#include <cuda_bf16.h>

// Problem shape (fixed)
#define HNUM 32
#define SLEN 8192
#define DDIM 128
#define LCAP 2048
#define OBS  16
#define QNUM 64

// -------- scratch (no allocations allowed) --------
__device__ float g_priority[HNUM * SLEN];   // 1 MB
__device__ int   g_keep[HNUM * LCAP];       // 256 KB

// Output layout (float32, concatenated): k_cache, v_cache, attn_history_c, pos
#define OUT_K  ((size_t)0)
#define OUT_V  ((size_t)HNUM * LCAP * DDIM)
#define OUT_AH ((size_t)2 * HNUM * LCAP * DDIM)
#define OUT_POS (OUT_AH + (size_t)HNUM * LCAP)

// ============================================================
// Kernel 1: priority[h][s] = mean over last OBS queries of attn[h][q][s]
// Association replicates XLA:GPU column-reduction warp shuffle-down tree
// (offset-16 step adds exact-neutral 0.0; then offsets 8,4,2,1):
//   r1[y] = e[y] + e[y+8]
//   r2[y] = r1[y] + r1[y+4]
//   r3[y] = r2[y] + r2[y+2]
//   sum   = r3[0] + r3[1]
// then * 1/16 (exact power of two).
// ============================================================
__global__ void priority_kernel(const float* __restrict__ attn) {
    int i = blockIdx.x * blockDim.x + threadIdx.x;
    if (i >= HNUM * SLEN) return;
    int h = i >> 13;
    int s = i & (SLEN - 1);
    const float* base = attn + ((size_t)(h * QNUM + (QNUM - OBS))) * SLEN + s;

    float e[OBS];
#pragma unroll
    for (int q = 0; q < OBS; ++q)
        e[q] = base[(size_t)q * SLEN];

    float r1[8], r2[4], r3[2];
#pragma unroll
    for (int j = 0; j < 8; ++j) r1[j] = __fadd_rn(e[j], e[j + 8]);
#pragma unroll
    for (int j = 0; j < 4; ++j) r2[j] = __fadd_rn(r1[j], r1[j + 4]);
#pragma unroll
    for (int j = 0; j < 2; ++j) r3[j] = __fadd_rn(r2[j], r2[j + 2]);
    float sum = __fadd_rn(r3[0], r3[1]);

    g_priority[i] = sum * 0.0625f;
}

// ============================================================
// Block-wide exclusive scan over 1024 threads (32 warps)
// ============================================================
__device__ __forceinline__ int block_exscan(int v, int* warp_s) {
    __syncthreads();  // protect warp_s reuse between calls
    int lane = threadIdx.x & 31;
    int wid  = threadIdx.x >> 5;
    int x = v;
#pragma unroll
    for (int o = 1; o < 32; o <<= 1) {
        int y = __shfl_up_sync(0xFFFFFFFFu, x, o);
        if (lane >= o) x += y;
    }
    if (lane == 31) warp_s[wid] = x;   // inclusive warp sum
    __syncthreads();
    if (wid == 0) {
        int w = warp_s[lane];
#pragma unroll
        for (int o = 1; o < 32; o <<= 1) {
            int y = __shfl_up_sync(0xFFFFFFFFu, w, o);
            if (lane >= o) w += y;
        }
        warp_s[lane] = w;              // inclusive scan of warp sums
    }
    __syncthreads();
    int woff = (wid == 0) ? 0 : warp_s[wid - 1];
    return woff + x - v;               // exclusive
}

// ============================================================
// Kernel 2: per-head pooling + exact top-L selection (1 block / head)
//
// Cumsum replicates XLA ReduceWindowRewriter(base_length=16) applied to
// the cumulative-sum reduce_window (jnp.cumsum on the reduce_window path)
// — validated by round-9's 6x rel_err drop:
//   inner[i]  = left-fold of p within its 16-block (per-element, seq)
//   T0[u]     = inner[16u+15]                        (512 block totals)
//   F[u]      = left-fold of T0 within its 16-superblock
//   T1[v]     = F[16v+15]                            (32 totals)
//   G[v]      = left-fold of T1 within its 16-super2block
//   T2[w]     = G[16w+15]                            (2 totals)
//   I2[0]=T2[0]; I2[1]=fl(T2[0]+T2[1])               (naive len-2 scan)
//   Incl32[v]  = (v<16) ? G[v] : fl(I2[0]   + G[v])
//   Incl512[u] = (u<16) ? F[u] : fl(Incl32[u/16-1] + F[u])
//   cinc[i]    = (i<16) ? inner[i] : fl(Incl512[i/16-1] + inner[i])
// ============================================================
#define SEL_SMEM_BYTES ((SLEN*4)*4 + 512*4 + 512*4 + 32*4 + 32*4 + 2*4 + 256*4 + 32*4 + 16 + 64)

extern "C" __global__ void __launch_bounds__(1024, 1)
select_kernel(float* __restrict__ out) {
    extern __shared__ unsigned char smem_raw[];
    float*    p      = (float*)smem_raw;          // [8192]
    float*    inner  = p + SLEN;                  // [8192]
    float*    cinc   = inner + SLEN;              // [8192]
    unsigned* u      = (unsigned*)(cinc + SLEN);  // [8192]
    float*    F      = (float*)(u + SLEN);        // [512]
    float*    S512   = F + 512;                   // [512] Incl512
    float*    G      = S512 + 512;                // [32]
    float*    S32    = G + 32;                    // [32] Incl32
    float*    I2     = S32 + 32;                  // [2]
    unsigned* hist   = (unsigned*)(I2 + 2);       // [256]
    int*      warp_s = (int*)(hist + 256);        // [32]
    volatile unsigned* bc = (volatile unsigned*)(warp_s + 32);

    const int h   = blockIdx.x;
    const int tid = threadIdx.x;

    // load priority into smem
    for (int i = tid; i < SLEN; i += 1024)
        p[i] = g_priority[h * SLEN + i];
    __syncthreads();

    // ---- level 0: per-16-block sequential fold partials ----
    if (tid < 512) {
        int b = tid * 16;
        float acc = 0.0f;
#pragma unroll
        for (int j = 0; j < 16; ++j) {
            acc = __fadd_rn(acc, p[b + j]);
            inner[b + j] = acc;
        }
    }
    __syncthreads();

    // ---- level 1: fold partials over T0 within superblocks ----
    if (tid < 32) {
        float acc = 0.0f;
#pragma unroll
        for (int j = 0; j < 16; ++j) {
            int uu = tid * 16 + j;
            acc = __fadd_rn(acc, inner[uu * 16 + 15]);  // T0[uu]
            F[uu] = acc;
        }
    }
    __syncthreads();

    // ---- level 2 + top: tiny, single thread ----
    if (tid == 0) {
        for (int w = 0; w < 2; ++w) {
            float acc = 0.0f;
            for (int j = 0; j < 16; ++j) {
                int v = w * 16 + j;
                acc = __fadd_rn(acc, F[v * 16 + 15]);   // T1[v]
                G[v] = acc;
            }
        }
        I2[0] = G[15];                                   // T2[0]
        I2[1] = __fadd_rn(G[15], G[31]);                 // fl(T2[0]+T2[1])
        for (int v = 0; v < 32; ++v)
            S32[v] = (v < 16) ? G[v] : __fadd_rn(I2[0], G[v]);
    }
    __syncthreads();

    // ---- Incl512 ----
    if (tid < 512) {
        int v = tid >> 4;
        S512[tid] = (v == 0) ? F[tid] : __fadd_rn(S32[v - 1], F[tid]);
    }
    __syncthreads();

    // ---- final inclusive cumsum ----
    for (int i = tid; i < SLEN; i += 1024) {
        int uu = i >> 4;
        cinc[i] = (uu == 0) ? inner[i] : __fadd_rn(S512[uu - 1], inner[i]);
    }
    __syncthreads();

    // ---- pooled = (c0[hi]-c0[lo]) / (hi-lo); last OBS forced to 1.0 ----
    // c0[j] = (j==0) ? 0 : cinc[j-1]
    for (int i = tid; i < SLEN; i += 1024) {
        int lo = (i - 2 < 0) ? 0 : i - 2;
        int hi = (i + 3 > SLEN) ? SLEN : i + 3;
        float chi = cinc[hi - 1];                      // hi >= 3 always
        float clo = (lo == 0) ? 0.0f : cinc[lo - 1];
        float w   = __fadd_rn(chi, -clo);              // IEEE subtract
        float pv  = __fdiv_rn(w, (float)(hi - lo));    // IEEE divide
        if (i >= SLEN - OBS) pv = 1.0f;
        u[i] = __float_as_uint(pv);                    // all >= 0 -> u32 order == float order
    }
    __syncthreads();

    // ---- 4-pass radix select: threshold T = L-th largest ----
    unsigned prefix = 0;
    int bitsdone = 0;
    unsigned K = LCAP;
#pragma unroll
    for (int pass = 0; pass < 4; ++pass) {
        int shift = 24 - pass * 8;
        if (tid < 256) hist[tid] = 0;
        __syncthreads();
        for (int i = tid; i < SLEN; i += 1024) {
            unsigned v = u[i];
            bool act = (bitsdone == 0) || ((v >> (32 - bitsdone)) == prefix);
            unsigned b = (v >> shift) & 255u;
            unsigned key = act ? b : 0xFFFFFFFFu;
            unsigned mask = __match_any_sync(0xFFFFFFFFu, key);
            if (act) {
                int leader = __ffs(mask) - 1;
                if ((int)(threadIdx.x & 31) == leader)
                    atomicAdd(&hist[b], (unsigned)__popc(mask));
            }
        }
        __syncthreads();
        if (tid == 0) {
            unsigned krem = K;
            int b = 255;
            for (; b > 0; --b) {
                if (hist[b] >= krem) break;
                krem -= hist[b];
            }
            bc[0] = (unsigned)b;
            bc[1] = krem;
        }
        __syncthreads();
        prefix = (prefix << 8) | bc[0];
        K = bc[1];
        bitsdone += 8;
        __syncthreads();
    }
    const unsigned T = prefix;      // threshold value (bits)
    const int E_need = (int)K;      // how many equal-to-T to take (lowest indices first)

    // ---- compaction in ascending index order (== required sort) ----
    const int base = tid * 8;
    int myeq = 0;
#pragma unroll
    for (int j = 0; j < 8; ++j) myeq += (u[base + j] == T);
    int eqoff = block_exscan(myeq, warp_s);

    int selflag[8];
    int mysel = 0;
    {
        int erun = eqoff;
#pragma unroll
        for (int j = 0; j < 8; ++j) {
            unsigned v = u[base + j];
            bool s_ = (v > T) || (v == T && erun < E_need);
            if (v == T) erun++;
            selflag[j] = s_ ? 1 : 0;
            mysel += selflag[j];
        }
    }
    int pos = block_exscan(mysel, warp_s);

    float* out_ah  = out + OUT_AH  + (size_t)h * LCAP;
    float* out_pos = out + OUT_POS + (size_t)h * LCAP;
#pragma unroll
    for (int j = 0; j < 8; ++j) {
        if (selflag[j]) {
            int i = base + j;
            g_keep[h * LCAP + pos] = i;
            out_ah[pos]  = p[i];
            out_pos[pos] = (float)i;
            pos++;
        }
    }
}

// ============================================================
// Kernel 3: K/V row gather (full-chip grid for bandwidth)
// ============================================================
__global__ void __launch_bounds__(256)
gather_kernel(const float* __restrict__ kval, const float* __restrict__ vval,
              float* __restrict__ out) {
    int h     = blockIdx.x >> 4;
    int chunk = blockIdx.x & 15;
    int rgrp  = threadIdx.x >> 5;   // 0..7
    int lane  = threadIdx.x & 31;   // 32 lanes x float4 = 128 floats/row

    float4* outk = (float4*)(out + OUT_K);
    float4* outv = (float4*)(out + OUT_V);

#pragma unroll 4
    for (int r = rgrp; r < 128; r += 8) {
        int j = chunk * 128 + r;
        int idx = g_keep[h * LCAP + j];
        const float4* ksrc = (const float4*)(kval + ((size_t)h * SLEN + idx) * DDIM);
        const float4* vsrc = (const float4*)(vval + ((size_t)h * SLEN + idx) * DDIM);
        size_t o = ((size_t)h * LCAP + j) * (DDIM / 4);
        outk[o + lane] = ksrc[lane];
        outv[o + lane] = vsrc[lane];
    }
}

// ============================================================
extern "C" void kernel_launch(void* const* d_in, const int* in_sizes, int n_in,
                              void* d_out, int out_size) {
    const float* attn  = (const float*)d_in[0];
    const float* k_val = (const float*)d_in[1];
    const float* v_val = (const float*)d_in[2];
    float* out = (float*)d_out;

    cudaFuncSetAttribute(select_kernel,
                         cudaFuncAttributeMaxDynamicSharedMemorySize,
                         SEL_SMEM_BYTES);

    priority_kernel<<<(HNUM * SLEN + 255) / 256, 256>>>(attn);
    select_kernel<<<HNUM, 1024, SEL_SMEM_BYTES>>>(out);
    gather_kernel<<<HNUM * 16, 256>>>(k_val, v_val, out);
}

// round 16
// speedup vs baseline: 1.0917x; 1.0917x over previous
#include <cuda_runtime.h>
#include <cuda_bf16.h>

// Problem shape (fixed)
#define HNUM 32
#define SLEN 8192
#define DDIM 128
#define LCAP 2048
#define OBS  16
#define QNUM 64

// -------- scratch (no allocations allowed) --------
__device__ float g_priority[HNUM * SLEN];   // 1 MB
__device__ int   g_keep[HNUM * LCAP];       // 256 KB

// Output layout (float32, concatenated): k_cache, v_cache, attn_history_c, pos
#define OUT_K  ((size_t)0)
#define OUT_V  ((size_t)HNUM * LCAP * DDIM)
#define OUT_AH ((size_t)2 * HNUM * LCAP * DDIM)
#define OUT_POS (OUT_AH + (size_t)HNUM * LCAP)

// ============================================================
// Kernel 1: priority[h][s] = mean over last OBS queries of attn[h][q][s]
// float4 vectorized: thread covers 4 consecutive s. Association (per lane)
// replicates XLA:GPU column-reduction warp shuffle-down tree — FROZEN:
//   r1[y]=e[y]+e[y+8]; r2[y]=r1[y]+r1[y+4]; r3[y]=r2[y]+r2[y+2];
//   sum=r3[0]+r3[1]; then * 1/16 (exact).
// ============================================================
__global__ void __launch_bounds__(256)
priority_kernel(const float* __restrict__ attn) {
    int i = blockIdx.x * blockDim.x + threadIdx.x;     // 65536 threads
    if (i >= HNUM * SLEN / 4) return;
    int h  = i >> 11;                                  // 2048 float4 per head
    int s4 = (i & 2047) << 2;
    const float4* base = (const float4*)(attn
        + ((size_t)(h * QNUM + (QNUM - OBS))) * SLEN + s4);

    float4 e[OBS];
#pragma unroll
    for (int q = 0; q < OBS; ++q)
        e[q] = base[(size_t)q * (SLEN / 4)];

    float4 r1[8], r2[4], r3[2], sum;
#pragma unroll
    for (int j = 0; j < 8; ++j) {
        r1[j].x = __fadd_rn(e[j].x, e[j + 8].x);
        r1[j].y = __fadd_rn(e[j].y, e[j + 8].y);
        r1[j].z = __fadd_rn(e[j].z, e[j + 8].z);
        r1[j].w = __fadd_rn(e[j].w, e[j + 8].w);
    }
#pragma unroll
    for (int j = 0; j < 4; ++j) {
        r2[j].x = __fadd_rn(r1[j].x, r1[j + 4].x);
        r2[j].y = __fadd_rn(r1[j].y, r1[j + 4].y);
        r2[j].z = __fadd_rn(r1[j].z, r1[j + 4].z);
        r2[j].w = __fadd_rn(r1[j].w, r1[j + 4].w);
    }
#pragma unroll
    for (int j = 0; j < 2; ++j) {
        r3[j].x = __fadd_rn(r2[j].x, r2[j + 2].x);
        r3[j].y = __fadd_rn(r2[j].y, r2[j + 2].y);
        r3[j].z = __fadd_rn(r2[j].z, r2[j + 2].z);
        r3[j].w = __fadd_rn(r2[j].w, r2[j + 2].w);
    }
    sum.x = __fadd_rn(r3[0].x, r3[1].x) * 0.0625f;
    sum.y = __fadd_rn(r3[0].y, r3[1].y) * 0.0625f;
    sum.z = __fadd_rn(r3[0].z, r3[1].z) * 0.0625f;
    sum.w = __fadd_rn(r3[0].w, r3[1].w) * 0.0625f;

    ((float4*)g_priority)[i] = sum;
}

// ============================================================
// Block-wide exclusive scan over 1024 threads (32 warps)
// ============================================================
__device__ __forceinline__ int block_exscan(int v, int* warp_s) {
    __syncthreads();  // protect warp_s reuse between calls
    int lane = threadIdx.x & 31;
    int wid  = threadIdx.x >> 5;
    int x = v;
#pragma unroll
    for (int o = 1; o < 32; o <<= 1) {
        int y = __shfl_up_sync(0xFFFFFFFFu, x, o);
        if (lane >= o) x += y;
    }
    if (lane == 31) warp_s[wid] = x;   // inclusive warp sum
    __syncthreads();
    if (wid == 0) {
        int w = warp_s[lane];
#pragma unroll
        for (int o = 1; o < 32; o <<= 1) {
            int y = __shfl_up_sync(0xFFFFFFFFu, w, o);
            if (lane >= o) w += y;
        }
        warp_s[lane] = w;              // inclusive scan of warp sums
    }
    __syncthreads();
    int woff = (wid == 0) ? 0 : warp_s[wid - 1];
    return woff + x - v;               // exclusive
}

// ============================================================
// Kernel 2: per-head pooling + exact top-L selection (1 block / head)
// Cumsum = XLA ReduceWindowRewriter(base_length=16) hierarchy — FROZEN
// (validated: rel_err 5.76e-8 pass in round 12).
// ============================================================
#define SEL_SMEM_BYTES ((SLEN*4)*4 + 512*4 + 512*4 + 32*4 + 32*4 + 2*4 + 256*4 + 32*4 + 16 + 64)

extern "C" __global__ void __launch_bounds__(1024, 1)
select_kernel(float* __restrict__ out) {
    extern __shared__ unsigned char smem_raw[];
    float*    p      = (float*)smem_raw;          // [8192]
    float*    inner  = p + SLEN;                  // [8192]
    float*    cinc   = inner + SLEN;              // [8192]
    unsigned* u      = (unsigned*)(cinc + SLEN);  // [8192]
    float*    F      = (float*)(u + SLEN);        // [512]
    float*    S512   = F + 512;                   // [512] Incl512
    float*    G      = S512 + 512;                // [32]
    float*    S32    = G + 32;                    // [32] Incl32
    float*    I2     = S32 + 32;                  // [2]
    unsigned* hist   = (unsigned*)(I2 + 2);       // [256]
    int*      warp_s = (int*)(hist + 256);        // [32]
    volatile unsigned* bc = (volatile unsigned*)(warp_s + 32);

    const int h   = blockIdx.x;
    const int tid = threadIdx.x;

    // load priority into smem (vectorized)
    {
        const float4* src = (const float4*)(g_priority + h * SLEN);
        float4*       dst = (float4*)p;
        for (int i = tid; i < SLEN / 4; i += 1024)
            dst[i] = src[i];
    }
    __syncthreads();

    // ---- level 0: per-16-block sequential fold partials ----
    if (tid < 512) {
        int b = tid * 16;
        float acc = 0.0f;
#pragma unroll
        for (int j = 0; j < 16; ++j) {
            acc = __fadd_rn(acc, p[b + j]);
            inner[b + j] = acc;
        }
    }
    __syncthreads();

    // ---- level 1: fold partials over T0 within superblocks ----
    if (tid < 32) {
        float acc = 0.0f;
#pragma unroll
        for (int j = 0; j < 16; ++j) {
            int uu = tid * 16 + j;
            acc = __fadd_rn(acc, inner[uu * 16 + 15]);  // T0[uu]
            F[uu] = acc;
        }
    }
    __syncthreads();

    // ---- level 2 + top: tiny, single thread ----
    if (tid == 0) {
        for (int w = 0; w < 2; ++w) {
            float acc = 0.0f;
            for (int j = 0; j < 16; ++j) {
                int v = w * 16 + j;
                acc = __fadd_rn(acc, F[v * 16 + 15]);   // T1[v]
                G[v] = acc;
            }
        }
        I2[0] = G[15];                                   // T2[0]
        I2[1] = __fadd_rn(G[15], G[31]);                 // fl(T2[0]+T2[1])
        for (int v = 0; v < 32; ++v)
            S32[v] = (v < 16) ? G[v] : __fadd_rn(I2[0], G[v]);
    }
    __syncthreads();

    // ---- Incl512 ----
    if (tid < 512) {
        int v = tid >> 4;
        S512[tid] = (v == 0) ? F[tid] : __fadd_rn(S32[v - 1], F[tid]);
    }
    __syncthreads();

    // ---- final inclusive cumsum ----
    for (int i = tid; i < SLEN; i += 1024) {
        int uu = i >> 4;
        cinc[i] = (uu == 0) ? inner[i] : __fadd_rn(S512[uu - 1], inner[i]);
    }
    __syncthreads();

    // ---- pooled = (c0[hi]-c0[lo]) / (hi-lo); last OBS forced to 1.0 ----
    for (int i = tid; i < SLEN; i += 1024) {
        int lo = (i - 2 < 0) ? 0 : i - 2;
        int hi = (i + 3 > SLEN) ? SLEN : i + 3;
        float chi = cinc[hi - 1];                      // hi >= 3 always
        float clo = (lo == 0) ? 0.0f : cinc[lo - 1];
        float w   = __fadd_rn(chi, -clo);              // IEEE subtract
        float pv  = __fdiv_rn(w, (float)(hi - lo));    // IEEE divide
        if (i >= SLEN - OBS) pv = 1.0f;
        u[i] = __float_as_uint(pv);                    // all >= 0 -> u32 order == float order
    }
    __syncthreads();

    // ---- 4-pass radix select: threshold T = L-th largest ----
    unsigned prefix = 0;
    int bitsdone = 0;
    unsigned K = LCAP;
#pragma unroll
    for (int pass = 0; pass < 4; ++pass) {
        int shift = 24 - pass * 8;
        if (tid < 256) hist[tid] = 0;
        __syncthreads();
        for (int i = tid; i < SLEN; i += 1024) {
            unsigned v = u[i];
            bool act = (bitsdone == 0) || ((v >> (32 - bitsdone)) == prefix);
            unsigned b = (v >> shift) & 255u;
            unsigned key = act ? b : 0xFFFFFFFFu;
            unsigned mask = __match_any_sync(0xFFFFFFFFu, key);
            if (act) {
                int leader = __ffs(mask) - 1;
                if ((int)(threadIdx.x & 31) == leader)
                    atomicAdd(&hist[b], (unsigned)__popc(mask));
            }
        }
        __syncthreads();
        if (tid == 0) {
            unsigned krem = K;
            int b = 255;
            for (; b > 0; --b) {
                if (hist[b] >= krem) break;
                krem -= hist[b];
            }
            bc[0] = (unsigned)b;
            bc[1] = krem;
        }
        __syncthreads();
        prefix = (prefix << 8) | bc[0];
        K = bc[1];
        bitsdone += 8;
        __syncthreads();
    }
    const unsigned T = prefix;      // threshold value (bits)
    const int E_need = (int)K;      // how many equal-to-T to take (lowest indices first)

    // ---- compaction in ascending index order (== required sort) ----
    const int base = tid * 8;
    int myeq = 0;
#pragma unroll
    for (int j = 0; j < 8; ++j) myeq += (u[base + j] == T);
    int eqoff = block_exscan(myeq, warp_s);

    int selflag[8];
    int mysel = 0;
    {
        int erun = eqoff;
#pragma unroll
        for (int j = 0; j < 8; ++j) {
            unsigned v = u[base + j];
            bool s_ = (v > T) || (v == T && erun < E_need);
            if (v == T) erun++;
            selflag[j] = s_ ? 1 : 0;
            mysel += selflag[j];
        }
    }
    int pos = block_exscan(mysel, warp_s);

    float* out_ah  = out + OUT_AH  + (size_t)h * LCAP;
    float* out_pos = out + OUT_POS + (size_t)h * LCAP;
#pragma unroll
    for (int j = 0; j < 8; ++j) {
        if (selflag[j]) {
            int i = base + j;
            g_keep[h * LCAP + pos] = i;
            out_ah[pos]  = p[i];
            out_pos[pos] = (float)i;
            pos++;
        }
    }
}

// ============================================================
// Kernel 3: K/V row gather.
// 512 blocks x 256 threads; block = (head, chunk of 128 rows);
// warp = 16 rows. Indices hoisted up-front (breaks the dependent
// idx->gather chain); streaming load/store hints (no reuse).
// ============================================================
__global__ void __launch_bounds__(256)
gather_kernel(const float* __restrict__ kval, const float* __restrict__ vval,
              float* __restrict__ out) {
    int h     = blockIdx.x >> 4;
    int chunk = blockIdx.x & 15;
    int wid   = threadIdx.x >> 5;   // 0..7
    int lane  = threadIdx.x & 31;   // 32 lanes x float4 = 512B row

    const int jbase = chunk * 128 + wid * 16;

    // hoist all 16 row indices (broadcast loads, fully pipelined)
    int idx[16];
#pragma unroll
    for (int t = 0; t < 16; ++t)
        idx[t] = __ldg(&g_keep[h * LCAP + jbase + t]);

    const float4* kbase = (const float4*)(kval + (size_t)h * SLEN * DDIM);
    const float4* vbase = (const float4*)(vval + (size_t)h * SLEN * DDIM);
    float4* outk = (float4*)(out + OUT_K) + ((size_t)h * LCAP + jbase) * (DDIM / 4);
    float4* outv = (float4*)(out + OUT_V) + ((size_t)h * LCAP + jbase) * (DDIM / 4);

#pragma unroll 4
    for (int t = 0; t < 16; ++t) {
        float4 kv = __ldcs(kbase + (size_t)idx[t] * (DDIM / 4) + lane);
        float4 vv = __ldcs(vbase + (size_t)idx[t] * (DDIM / 4) + lane);
        __stcs(outk + (size_t)t * (DDIM / 4) + lane, kv);
        __stcs(outv + (size_t)t * (DDIM / 4) + lane, vv);
    }
}

// ============================================================
extern "C" void kernel_launch(void* const* d_in, const int* in_sizes, int n_in,
                              void* d_out, int out_size) {
    const float* attn  = (const float*)d_in[0];
    const float* k_val = (const float*)d_in[1];
    const float* v_val = (const float*)d_in[2];
    float* out = (float*)d_out;

    cudaFuncSetAttribute(select_kernel,
                         cudaFuncAttributeMaxDynamicSharedMemorySize,
                         SEL_SMEM_BYTES);

    priority_kernel<<<(HNUM * SLEN / 4 + 255) / 256, 256>>>(attn);
    select_kernel<<<HNUM, 1024, SEL_SMEM_BYTES>>>(out);
    gather_kernel<<<HNUM * 16, 256>>>(k_val, v_val, out);
}